// round 11
// baseline (speedup 1.0000x reference)
#include <cuda_runtime.h>

// Problem constants (fixed dataset: M=262144, K_DIM=V_DIM=256)
#define M_ROWS 262144
#define DIM    256
#define NB     444               // 3 CTAs x 148 SMs: exactly one resident wave
#define TPB    256               // threads per block (8 warps)
#define NWARP  (TPB / 32)
#define TOTW   (NB * NWARP)      // 3552 warps
#define GPW    18                // exact 4-row groups per warp (3552*18 = 63936)
#define REM0   (TOTW * GPW * 4)  // 255744: first remainder row
#define SCALE  0.0625f           // 1/sqrt(256)

#define NR     74                // reduce blocks
#define RPRB   (NB / NR)         // 6 partial-rows per reduce block

// ---- scratch (allocation-free: __device__ globals) ----
__device__ float g_pwv[NB][DIM];     // per-block partial  sum e_w * V
__device__ float g_prv[NB][DIM];     // per-block partial  sum e_r * V
__device__ float g_psc[NB][3];       // per-block partial  {S_w, S_r, C}
__device__ float g_pwv2[NR][DIM];    // stage-A reduced partials
__device__ float g_prv2[NR][DIM];
__device__ float g_psc2[NR][3];
__device__ unsigned int g_ticket2 = 0;  // reduce-stage completion counter

// ============================================================
// Fused pass: K row -> score -> exp weight -> weighted V row.
// Unnormalized softmax (scores ~N(0,1): fp32-safe without max).
// Reads K + V = 512 MB exactly once. 4-row groups with 16
// front-batched LDG.128 per warp; perfectly balanced work
// (every warp: exactly 18 groups + 1-2 remainder rows).
// Measured: 80.3us, DRAM=85.1%. DO NOT TOUCH.
// ============================================================
__global__ __launch_bounds__(TPB, 3) void k_fused(const float* __restrict__ Kmat,
                                                  const float* __restrict__ Vmat,
                                                  const float* __restrict__ key,
                                                  const float* __restrict__ query) {
    const int warp = threadIdx.x >> 5;
    const int lane = threadIdx.x & 31;

    // lane l owns columns [8l, 8l+8)
    const float4* keyv = (const float4*)key;
    const float4* qryv = (const float4*)query;
    const float4  k0 = keyv[lane * 2], k1 = keyv[lane * 2 + 1];
    const float4  q0 = qryv[lane * 2], q1 = qryv[lane * 2 + 1];

    const int wgid = blockIdx.x * NWARP + warp;

    float awv[8] = {0, 0, 0, 0, 0, 0, 0, 0};
    float arv[8] = {0, 0, 0, 0, 0, 0, 0, 0};
    float sw = 0.f, sr = 0.f, cc = 0.f;

    // ---- Main: exactly GPW strided 4-row groups per warp ----
#pragma unroll 1
    for (int i = 0; i < GPW; ++i) {
        const int r = (wgid + i * TOTW) * 4;

        float4 A[4][2], Vv[4][2];
#pragma unroll
        for (int u = 0; u < 4; ++u) {
            const float4* pk = (const float4*)(Kmat + (size_t)(r + u) * DIM) + lane * 2;
            const float4* pv = (const float4*)(Vmat + (size_t)(r + u) * DIM) + lane * 2;
            A[u][0]  = pk[0];
            A[u][1]  = pk[1];
            Vv[u][0] = pv[0];
            Vv[u][1] = pv[1];
        }

        float dw[4], dr[4];
#pragma unroll
        for (int u = 0; u < 4; ++u) {
            float4 a = A[u][0], b = A[u][1];
            dw[u] = a.x * k0.x + a.y * k0.y + a.z * k0.z + a.w * k0.w
                  + b.x * k1.x + b.y * k1.y + b.z * k1.z + b.w * k1.w;
            dr[u] = a.x * q0.x + a.y * q0.y + a.z * q0.z + a.w * q0.w
                  + b.x * q1.x + b.y * q1.y + b.z * q1.z + b.w * q1.w;
        }
#pragma unroll
        for (int off = 16; off > 0; off >>= 1) {
#pragma unroll
            for (int u = 0; u < 4; ++u) {
                dw[u] += __shfl_xor_sync(0xffffffffu, dw[u], off);
                dr[u] += __shfl_xor_sync(0xffffffffu, dr[u], off);
            }
        }

#pragma unroll
        for (int u = 0; u < 4; ++u) {
            const float w = __expf(dw[u] * SCALE);
            const float e = __expf(dr[u] * SCALE);
            sw += w;
            sr += e;
            cc += w * e;
            float4 a = Vv[u][0], b = Vv[u][1];
            awv[0] += w * a.x;  awv[1] += w * a.y;
            awv[2] += w * a.z;  awv[3] += w * a.w;
            awv[4] += w * b.x;  awv[5] += w * b.y;
            awv[6] += w * b.z;  awv[7] += w * b.w;
            arv[0] += e * a.x;  arv[1] += e * a.y;
            arv[2] += e * a.z;  arv[3] += e * a.w;
            arv[4] += e * b.x;  arv[5] += e * b.y;
            arv[6] += e * b.z;  arv[7] += e * b.w;
        }
    }

    // ---- Remainder: rows REM0..M-1, one row per warp, <=2 passes ----
    {
        const int r1 = REM0 + wgid;              // always < M_ROWS
        const int r2 = r1 + TOTW;                // valid iff wgid < 2848
        const bool has2 = (r2 < M_ROWS);

        const float4* pk1 = (const float4*)(Kmat + (size_t)r1 * DIM) + lane * 2;
        const float4* pv1 = (const float4*)(Vmat + (size_t)r1 * DIM) + lane * 2;
        float4 a0 = pk1[0], a1 = pk1[1];
        float4 v0 = pv1[0], v1 = pv1[1];

        float4 b0 = {0, 0, 0, 0}, b1 = {0, 0, 0, 0};
        float4 u0 = {0, 0, 0, 0}, u1 = {0, 0, 0, 0};
        if (has2) {
            const float4* pk2 = (const float4*)(Kmat + (size_t)r2 * DIM) + lane * 2;
            const float4* pv2 = (const float4*)(Vmat + (size_t)r2 * DIM) + lane * 2;
            b0 = pk2[0];
            b1 = pk2[1];
            u0 = pv2[0];
            u1 = pv2[1];
        }

        float dw1 = a0.x * k0.x + a0.y * k0.y + a0.z * k0.z + a0.w * k0.w
                  + a1.x * k1.x + a1.y * k1.y + a1.z * k1.z + a1.w * k1.w;
        float dr1 = a0.x * q0.x + a0.y * q0.y + a0.z * q0.z + a0.w * q0.w
                  + a1.x * q1.x + a1.y * q1.y + a1.z * q1.z + a1.w * q1.w;
        float dw2 = b0.x * k0.x + b0.y * k0.y + b0.z * k0.z + b0.w * k0.w
                  + b1.x * k1.x + b1.y * k1.y + b1.z * k1.z + b1.w * k1.w;
        float dr2 = b0.x * q0.x + b0.y * q0.y + b0.z * q0.z + b0.w * q0.w
                  + b1.x * q1.x + b1.y * q1.y + b1.z * q1.z + b1.w * q1.w;
#pragma unroll
        for (int off = 16; off > 0; off >>= 1) {
            dw1 += __shfl_xor_sync(0xffffffffu, dw1, off);
            dr1 += __shfl_xor_sync(0xffffffffu, dr1, off);
            dw2 += __shfl_xor_sync(0xffffffffu, dw2, off);
            dr2 += __shfl_xor_sync(0xffffffffu, dr2, off);
        }
        const float w1 = __expf(dw1 * SCALE);
        const float e1 = __expf(dr1 * SCALE);
        const float w2 = has2 ? __expf(dw2 * SCALE) : 0.f;
        const float e2 = has2 ? __expf(dr2 * SCALE) : 0.f;
        sw += w1 + w2;
        sr += e1 + e2;
        cc += w1 * e1 + w2 * e2;

        awv[0] += w1 * v0.x + w2 * u0.x;  arv[0] += e1 * v0.x + e2 * u0.x;
        awv[1] += w1 * v0.y + w2 * u0.y;  arv[1] += e1 * v0.y + e2 * u0.y;
        awv[2] += w1 * v0.z + w2 * u0.z;  arv[2] += e1 * v0.z + e2 * u0.z;
        awv[3] += w1 * v0.w + w2 * u0.w;  arv[3] += e1 * v0.w + e2 * u0.w;
        awv[4] += w1 * v1.x + w2 * u1.x;  arv[4] += e1 * v1.x + e2 * u1.x;
        awv[5] += w1 * v1.y + w2 * u1.y;  arv[5] += e1 * v1.y + e2 * u1.y;
        awv[6] += w1 * v1.z + w2 * u1.z;  arv[6] += e1 * v1.z + e2 * u1.z;
        awv[7] += w1 * v1.w + w2 * u1.w;  arv[7] += e1 * v1.w + e2 * u1.w;
    }

    // Block reduction: warp w's lane l holds cols 8l..8l+7
    __shared__ float sh[NWARP][DIM];
    const int t = threadIdx.x;

#pragma unroll
    for (int j = 0; j < 8; ++j) sh[warp][lane * 8 + j] = awv[j];
    __syncthreads();
    {
        float s = 0.f;
#pragma unroll
        for (int w2 = 0; w2 < NWARP; ++w2) s += sh[w2][t];
        g_pwv[blockIdx.x][t] = s;
    }
    __syncthreads();
#pragma unroll
    for (int j = 0; j < 8; ++j) sh[warp][lane * 8 + j] = arv[j];
    __syncthreads();
    {
        float s = 0.f;
#pragma unroll
        for (int w2 = 0; w2 < NWARP; ++w2) s += sh[w2][t];
        g_prv[blockIdx.x][t] = s;
    }

    __shared__ float ssc[NWARP][3];
    if (lane == 0) { ssc[warp][0] = sw; ssc[warp][1] = sr; ssc[warp][2] = cc; }
    __syncthreads();
    if (t < 3) {
        float s = 0.f;
#pragma unroll
        for (int w2 = 0; w2 < NWARP; ++w2) s += ssc[w2][t];
        g_psc[blockIdx.x][t] = s;
    }
}

// ============================================================
// Merged tail: 74 blocks each fold 6 partial rows; the LAST
// block (fence+ticket over only 74 blocks) additionally folds
// the 74 stage-A rows (L2-hot) and writes the 256 outputs.
// Fixed summation order -> deterministic. One launch, one gap.
// ============================================================
__global__ __launch_bounds__(DIM) void k_tail(const float* __restrict__ value,
                                              float* __restrict__ out) {
    const int t  = threadIdx.x;
    const int b0 = blockIdx.x * RPRB;

    float wv = 0.f, rv = 0.f;
#pragma unroll
    for (int b = 0; b < RPRB; ++b) {
        wv += g_pwv[b0 + b][t];
        rv += g_prv[b0 + b][t];
    }
    g_pwv2[blockIdx.x][t] = wv;
    g_prv2[blockIdx.x][t] = rv;
    if (t < 3) {
        float s = 0.f;
#pragma unroll
        for (int b = 0; b < RPRB; ++b) s += g_psc[b0 + b][t];
        g_psc2[blockIdx.x][t] = s;
    }

    // Publish this block's stage-A row, then elect the last block.
    __shared__ unsigned int s_islast;
    __threadfence();
    __syncthreads();
    if (t == 0) {
        unsigned int tk = atomicAdd(&g_ticket2, 1u);
        s_islast = (tk == NR - 1) ? 1u : 0u;
    }
    __syncthreads();
    if (!s_islast) return;

    if (t == 0) g_ticket2 = 0;   // reset for next graph replay

    // Fold the 74 stage-A rows (all L2-hot; 148 loads/thread).
    float wvf = 0.f, rvf = 0.f;
#pragma unroll 2
    for (int b = 0; b < NR; ++b) {
        wvf += g_pwv2[b][t];
        rvf += g_prv2[b][t];
    }
    __shared__ float s3[3];
    if (t < 3) {
        float s = 0.f;
        for (int b = 0; b < NR; ++b) s += g_psc2[b][t];
        s3[t] = s;
    }
    __syncthreads();
    const float swT = s3[0], srT = s3[1], ccT = s3[2];
    out[t] = rvf / srT + (ccT / (swT * srT)) * (value[t] - wvf / swT);
}

// ============================================================
extern "C" void kernel_launch(void* const* d_in, const int* in_sizes, int n_in,
                              void* d_out, int out_size) {
    const float* key   = (const float*)d_in[0];
    const float* value = (const float*)d_in[1];
    const float* query = (const float*)d_in[2];
    const float* Kmat  = (const float*)d_in[3];
    const float* Vmat  = (const float*)d_in[4];
    float*       out   = (float*)d_out;

    k_fused<<<NB, TPB>>>(Kmat, Vmat, key, query);
    k_tail<<<NR, DIM>>>(value, out);
}

// round 12
// speedup vs baseline: 1.0504x; 1.0504x over previous
#include <cuda_runtime.h>

// Problem constants (fixed dataset: M=262144, K_DIM=V_DIM=256)
#define M_ROWS 262144
#define DIM    256
#define NB     444               // 3 CTAs x 148 SMs: exactly one resident wave
#define TPB    256               // threads per block (8 warps)
#define NWARP  (TPB / 32)
#define TOTW   (NB * NWARP)      // 3552 warps
#define GPW    18                // exact 4-row groups per warp (3552*18 = 63936)
#define REM0   (TOTW * GPW * 4)  // 255744: first remainder row
#define SCALE  0.0625f           // 1/sqrt(256)

#define NR     74                // stage-A reduce blocks
#define RPRB   (NB / NR)         // 6 partial-rows per reduce block

// ---- scratch (allocation-free: __device__ globals) ----
__device__ float g_pwv[NB][DIM];     // per-block partial  sum e_w * V
__device__ float g_prv[NB][DIM];     // per-block partial  sum e_r * V
__device__ float g_psc[NB][3];       // per-block partial  {S_w, S_r, C}
__device__ float g_pwv2[NR][DIM];    // stage-A reduced partials
__device__ float g_prv2[NR][DIM];
__device__ float g_psc2[NR][3];

// ============================================================
// Fused pass: K row -> score -> exp weight -> weighted V row.
// Unnormalized softmax (scores ~N(0,1): fp32-safe without max).
// Reads K + V = 512 MB exactly once. 4-row groups with 16
// front-batched LDG.128 per warp (measured-best MLP).
// Perfectly balanced: every warp does exactly 18 groups, then
// the 6400 remainder rows go 1-row-per-warp (<=2 passes).
// Measured: 80.3us, DRAM=85.1% (R10).
// ============================================================
__global__ __launch_bounds__(TPB, 3) void k_fused(const float* __restrict__ Kmat,
                                                  const float* __restrict__ Vmat,
                                                  const float* __restrict__ key,
                                                  const float* __restrict__ query) {
    const int warp = threadIdx.x >> 5;
    const int lane = threadIdx.x & 31;

    // lane l owns columns [8l, 8l+8)
    const float4* keyv = (const float4*)key;
    const float4* qryv = (const float4*)query;
    const float4  k0 = keyv[lane * 2], k1 = keyv[lane * 2 + 1];
    const float4  q0 = qryv[lane * 2], q1 = qryv[lane * 2 + 1];

    const int wgid = blockIdx.x * NWARP + warp;

    float awv[8] = {0, 0, 0, 0, 0, 0, 0, 0};
    float arv[8] = {0, 0, 0, 0, 0, 0, 0, 0};
    float sw = 0.f, sr = 0.f, cc = 0.f;

    // ---- Main: exactly GPW strided 4-row groups per warp ----
#pragma unroll 1
    for (int i = 0; i < GPW; ++i) {
        const int r = (wgid + i * TOTW) * 4;

        // Front-batch all 16 loads (K rows + V rows) for max MLP.
        float4 A[4][2], Vv[4][2];
#pragma unroll
        for (int u = 0; u < 4; ++u) {
            const float4* pk = (const float4*)(Kmat + (size_t)(r + u) * DIM) + lane * 2;
            const float4* pv = (const float4*)(Vmat + (size_t)(r + u) * DIM) + lane * 2;
            A[u][0]  = pk[0];
            A[u][1]  = pk[1];
            Vv[u][0] = pv[0];
            Vv[u][1] = pv[1];
        }

        float dw[4], dr[4];
#pragma unroll
        for (int u = 0; u < 4; ++u) {
            float4 a = A[u][0], b = A[u][1];
            dw[u] = a.x * k0.x + a.y * k0.y + a.z * k0.z + a.w * k0.w
                  + b.x * k1.x + b.y * k1.y + b.z * k1.z + b.w * k1.w;
            dr[u] = a.x * q0.x + a.y * q0.y + a.z * q0.z + a.w * q0.w
                  + b.x * q1.x + b.y * q1.y + b.z * q1.z + b.w * q1.w;
        }
        // Butterfly: every lane ends with the full dot products.
#pragma unroll
        for (int off = 16; off > 0; off >>= 1) {
#pragma unroll
            for (int u = 0; u < 4; ++u) {
                dw[u] += __shfl_xor_sync(0xffffffffu, dw[u], off);
                dr[u] += __shfl_xor_sync(0xffffffffu, dr[u], off);
            }
        }

#pragma unroll
        for (int u = 0; u < 4; ++u) {
            const float w = __expf(dw[u] * SCALE);
            const float e = __expf(dr[u] * SCALE);
            sw += w;
            sr += e;
            cc += w * e;
            float4 a = Vv[u][0], b = Vv[u][1];
            awv[0] += w * a.x;  awv[1] += w * a.y;
            awv[2] += w * a.z;  awv[3] += w * a.w;
            awv[4] += w * b.x;  awv[5] += w * b.y;
            awv[6] += w * b.z;  awv[7] += w * b.w;
            arv[0] += e * a.x;  arv[1] += e * a.y;
            arv[2] += e * a.z;  arv[3] += e * a.w;
            arv[4] += e * b.x;  arv[5] += e * b.y;
            arv[6] += e * b.z;  arv[7] += e * b.w;
        }
    }

    // ---- Remainder: rows REM0..M-1, one row per warp, <=2 passes ----
    {
        const int r1 = REM0 + wgid;              // always < M_ROWS
        const int r2 = r1 + TOTW;                // valid iff wgid < 2848
        const bool has2 = (r2 < M_ROWS);

        const float4* pk1 = (const float4*)(Kmat + (size_t)r1 * DIM) + lane * 2;
        const float4* pv1 = (const float4*)(Vmat + (size_t)r1 * DIM) + lane * 2;
        float4 a0 = pk1[0], a1 = pk1[1];
        float4 v0 = pv1[0], v1 = pv1[1];

        float4 b0 = {0, 0, 0, 0}, b1 = {0, 0, 0, 0};
        float4 u0 = {0, 0, 0, 0}, u1 = {0, 0, 0, 0};
        if (has2) {
            const float4* pk2 = (const float4*)(Kmat + (size_t)r2 * DIM) + lane * 2;
            const float4* pv2 = (const float4*)(Vmat + (size_t)r2 * DIM) + lane * 2;
            b0 = pk2[0];
            b1 = pk2[1];
            u0 = pv2[0];
            u1 = pv2[1];
        }

        float dw1 = a0.x * k0.x + a0.y * k0.y + a0.z * k0.z + a0.w * k0.w
                  + a1.x * k1.x + a1.y * k1.y + a1.z * k1.z + a1.w * k1.w;
        float dr1 = a0.x * q0.x + a0.y * q0.y + a0.z * q0.z + a0.w * q0.w
                  + a1.x * q1.x + a1.y * q1.y + a1.z * q1.z + a1.w * q1.w;
        float dw2 = b0.x * k0.x + b0.y * k0.y + b0.z * k0.z + b0.w * k0.w
                  + b1.x * k1.x + b1.y * k1.y + b1.z * k1.z + b1.w * k1.w;
        float dr2 = b0.x * q0.x + b0.y * q0.y + b0.z * q0.z + b0.w * q0.w
                  + b1.x * q1.x + b1.y * q1.y + b1.z * q1.z + b1.w * q1.w;
#pragma unroll
        for (int off = 16; off > 0; off >>= 1) {
            dw1 += __shfl_xor_sync(0xffffffffu, dw1, off);
            dr1 += __shfl_xor_sync(0xffffffffu, dr1, off);
            dw2 += __shfl_xor_sync(0xffffffffu, dw2, off);
            dr2 += __shfl_xor_sync(0xffffffffu, dr2, off);
        }
        const float w1 = __expf(dw1 * SCALE);
        const float e1 = __expf(dr1 * SCALE);
        const float w2 = has2 ? __expf(dw2 * SCALE) : 0.f;
        const float e2 = has2 ? __expf(dr2 * SCALE) : 0.f;
        sw += w1 + w2;
        sr += e1 + e2;
        cc += w1 * e1 + w2 * e2;

        awv[0] += w1 * v0.x + w2 * u0.x;  arv[0] += e1 * v0.x + e2 * u0.x;
        awv[1] += w1 * v0.y + w2 * u0.y;  arv[1] += e1 * v0.y + e2 * u0.y;
        awv[2] += w1 * v0.z + w2 * u0.z;  arv[2] += e1 * v0.z + e2 * u0.z;
        awv[3] += w1 * v0.w + w2 * u0.w;  arv[3] += e1 * v0.w + e2 * u0.w;
        awv[4] += w1 * v1.x + w2 * u1.x;  arv[4] += e1 * v1.x + e2 * u1.x;
        awv[5] += w1 * v1.y + w2 * u1.y;  arv[5] += e1 * v1.y + e2 * u1.y;
        awv[6] += w1 * v1.z + w2 * u1.z;  arv[6] += e1 * v1.z + e2 * u1.z;
        awv[7] += w1 * v1.w + w2 * u1.w;  arv[7] += e1 * v1.w + e2 * u1.w;
    }

    // Block reduction: warp w's lane l holds cols 8l..8l+7
    __shared__ float sh[NWARP][DIM];
    const int t = threadIdx.x;

#pragma unroll
    for (int j = 0; j < 8; ++j) sh[warp][lane * 8 + j] = awv[j];
    __syncthreads();
    {
        float s = 0.f;
#pragma unroll
        for (int w2 = 0; w2 < NWARP; ++w2) s += sh[w2][t];
        g_pwv[blockIdx.x][t] = s;
    }
    __syncthreads();
#pragma unroll
    for (int j = 0; j < 8; ++j) sh[warp][lane * 8 + j] = arv[j];
    __syncthreads();
    {
        float s = 0.f;
#pragma unroll
        for (int w2 = 0; w2 < NWARP; ++w2) s += sh[w2][t];
        g_prv[blockIdx.x][t] = s;
    }

    __shared__ float ssc[NWARP][3];
    if (lane == 0) { ssc[warp][0] = sw; ssc[warp][1] = sr; ssc[warp][2] = cc; }
    __syncthreads();
    if (t < 3) {
        float s = 0.f;
#pragma unroll
        for (int w2 = 0; w2 < NWARP; ++w2) s += ssc[w2][t];
        g_psc[blockIdx.x][t] = s;
    }
}

// ============================================================
// Stage A: 74 blocks each fold 6 partial rows (coalesced, L2-hot).
// ============================================================
__global__ __launch_bounds__(DIM) void k_reduce() {
    const int t  = threadIdx.x;
    const int b0 = blockIdx.x * RPRB;
    float wv = 0.f, rv = 0.f;
#pragma unroll
    for (int b = 0; b < RPRB; ++b) {
        wv += g_pwv[b0 + b][t];
        rv += g_prv[b0 + b][t];
    }
    g_pwv2[blockIdx.x][t] = wv;
    g_prv2[blockIdx.x][t] = rv;
    if (t < 3) {
        float s = 0.f;
#pragma unroll
        for (int b = 0; b < RPRB; ++b) s += g_psc[b0 + b][t];
        g_psc2[blockIdx.x][t] = s;
    }
}

// ============================================================
// Stage B: fold 74 rows, emit 256 outputs.
//   out = RV/S_r + C/(S_w*S_r) * (value - WV/S_w)
// ============================================================
__global__ __launch_bounds__(DIM) void k_final(const float* __restrict__ value,
                                               float* __restrict__ out) {
    const int t = threadIdx.x;
    float wv = 0.f, rv = 0.f;
#pragma unroll
    for (int b = 0; b < NR; ++b) {
        wv += g_pwv2[b][t];
        rv += g_prv2[b][t];
    }
    __shared__ float s3[3];
    if (t < 3) {
        float s = 0.f;
#pragma unroll
        for (int b = 0; b < NR; ++b) s += g_psc2[b][t];
        s3[t] = s;
    }
    __syncthreads();
    const float sw = s3[0], sr = s3[1], cc = s3[2];
    out[t] = rv / sr + (cc / (sw * sr)) * (value[t] - wv / sw);
}

// ============================================================
extern "C" void kernel_launch(void* const* d_in, const int* in_sizes, int n_in,
                              void* d_out, int out_size) {
    const float* key   = (const float*)d_in[0];
    const float* value = (const float*)d_in[1];
    const float* query = (const float*)d_in[2];
    const float* Kmat  = (const float*)d_in[3];
    const float* Vmat  = (const float*)d_in[4];
    float*       out   = (float*)d_out;

    k_fused<<<NB, TPB>>>(Kmat, Vmat, key, query);
    k_reduce<<<NR, DIM>>>();
    k_final<<<1, DIM>>>(value, out);
}

// round 13
// speedup vs baseline: 1.1446x; 1.0897x over previous
#include <cuda_runtime.h>

// Problem constants (fixed dataset: M=262144, K_DIM=V_DIM=256)
#define M_ROWS 262144
#define DIM    256
#define NB     444               // 3 CTAs x 148 SMs: exactly one resident wave
#define TPB    256               // threads per block (8 warps)
#define NWARP  (TPB / 32)
#define TOTW   (NB * NWARP)      // 3552 warps
#define GPW    18                // exact 4-row groups per warp (3552*18 = 63936)
#define REM0   (TOTW * GPW * 4)  // 255744: first remainder row
#define SCALE  0.0625f           // 1/sqrt(256)

#define TAILT  128               // threads per tail block

// ---- scratch (allocation-free: __device__ globals) ----
__device__ float g_pwv[NB][DIM];     // per-block partial  sum e_w * V
__device__ float g_prv[NB][DIM];     // per-block partial  sum e_r * V
__device__ float g_psc[NB][3];       // per-block partial  {S_w, S_r, C}

// ============================================================
// Fused pass: K row -> score -> exp weight -> weighted V row.
// Unnormalized softmax (scores ~N(0,1): fp32-safe without max).
// Reads K + V = 512 MB exactly once. 4-row groups with 16
// front-batched LDG.128 per warp; perfectly balanced work.
// Measured: 78.7us, DRAM=86.7% (R12). DO NOT TOUCH.
// ============================================================
__global__ __launch_bounds__(TPB, 3) void k_fused(const float* __restrict__ Kmat,
                                                  const float* __restrict__ Vmat,
                                                  const float* __restrict__ key,
                                                  const float* __restrict__ query) {
    const int warp = threadIdx.x >> 5;
    const int lane = threadIdx.x & 31;

    // lane l owns columns [8l, 8l+8)
    const float4* keyv = (const float4*)key;
    const float4* qryv = (const float4*)query;
    const float4  k0 = keyv[lane * 2], k1 = keyv[lane * 2 + 1];
    const float4  q0 = qryv[lane * 2], q1 = qryv[lane * 2 + 1];

    const int wgid = blockIdx.x * NWARP + warp;

    float awv[8] = {0, 0, 0, 0, 0, 0, 0, 0};
    float arv[8] = {0, 0, 0, 0, 0, 0, 0, 0};
    float sw = 0.f, sr = 0.f, cc = 0.f;

    // ---- Main: exactly GPW strided 4-row groups per warp ----
#pragma unroll 1
    for (int i = 0; i < GPW; ++i) {
        const int r = (wgid + i * TOTW) * 4;

        float4 A[4][2], Vv[4][2];
#pragma unroll
        for (int u = 0; u < 4; ++u) {
            const float4* pk = (const float4*)(Kmat + (size_t)(r + u) * DIM) + lane * 2;
            const float4* pv = (const float4*)(Vmat + (size_t)(r + u) * DIM) + lane * 2;
            A[u][0]  = pk[0];
            A[u][1]  = pk[1];
            Vv[u][0] = pv[0];
            Vv[u][1] = pv[1];
        }

        float dw[4], dr[4];
#pragma unroll
        for (int u = 0; u < 4; ++u) {
            float4 a = A[u][0], b = A[u][1];
            dw[u] = a.x * k0.x + a.y * k0.y + a.z * k0.z + a.w * k0.w
                  + b.x * k1.x + b.y * k1.y + b.z * k1.z + b.w * k1.w;
            dr[u] = a.x * q0.x + a.y * q0.y + a.z * q0.z + a.w * q0.w
                  + b.x * q1.x + b.y * q1.y + b.z * q1.z + b.w * q1.w;
        }
#pragma unroll
        for (int off = 16; off > 0; off >>= 1) {
#pragma unroll
            for (int u = 0; u < 4; ++u) {
                dw[u] += __shfl_xor_sync(0xffffffffu, dw[u], off);
                dr[u] += __shfl_xor_sync(0xffffffffu, dr[u], off);
            }
        }

#pragma unroll
        for (int u = 0; u < 4; ++u) {
            const float w = __expf(dw[u] * SCALE);
            const float e = __expf(dr[u] * SCALE);
            sw += w;
            sr += e;
            cc += w * e;
            float4 a = Vv[u][0], b = Vv[u][1];
            awv[0] += w * a.x;  awv[1] += w * a.y;
            awv[2] += w * a.z;  awv[3] += w * a.w;
            awv[4] += w * b.x;  awv[5] += w * b.y;
            awv[6] += w * b.z;  awv[7] += w * b.w;
            arv[0] += e * a.x;  arv[1] += e * a.y;
            arv[2] += e * a.z;  arv[3] += e * a.w;
            arv[4] += e * b.x;  arv[5] += e * b.y;
            arv[6] += e * b.z;  arv[7] += e * b.w;
        }
    }

    // ---- Remainder: rows REM0..M-1, one row per warp, <=2 passes ----
    {
        const int r1 = REM0 + wgid;              // always < M_ROWS
        const int r2 = r1 + TOTW;                // valid iff wgid < 2848
        const bool has2 = (r2 < M_ROWS);

        const float4* pk1 = (const float4*)(Kmat + (size_t)r1 * DIM) + lane * 2;
        const float4* pv1 = (const float4*)(Vmat + (size_t)r1 * DIM) + lane * 2;
        float4 a0 = pk1[0], a1 = pk1[1];
        float4 v0 = pv1[0], v1 = pv1[1];

        float4 b0 = {0, 0, 0, 0}, b1 = {0, 0, 0, 0};
        float4 u0 = {0, 0, 0, 0}, u1 = {0, 0, 0, 0};
        if (has2) {
            const float4* pk2 = (const float4*)(Kmat + (size_t)r2 * DIM) + lane * 2;
            const float4* pv2 = (const float4*)(Vmat + (size_t)r2 * DIM) + lane * 2;
            b0 = pk2[0];
            b1 = pk2[1];
            u0 = pv2[0];
            u1 = pv2[1];
        }

        float dw1 = a0.x * k0.x + a0.y * k0.y + a0.z * k0.z + a0.w * k0.w
                  + a1.x * k1.x + a1.y * k1.y + a1.z * k1.z + a1.w * k1.w;
        float dr1 = a0.x * q0.x + a0.y * q0.y + a0.z * q0.z + a0.w * q0.w
                  + a1.x * q1.x + a1.y * q1.y + a1.z * q1.z + a1.w * q1.w;
        float dw2 = b0.x * k0.x + b0.y * k0.y + b0.z * k0.z + b0.w * k0.w
                  + b1.x * k1.x + b1.y * k1.y + b1.z * k1.z + b1.w * k1.w;
        float dr2 = b0.x * q0.x + b0.y * q0.y + b0.z * q0.z + b0.w * q0.w
                  + b1.x * q1.x + b1.y * q1.y + b1.z * q1.z + b1.w * q1.w;
#pragma unroll
        for (int off = 16; off > 0; off >>= 1) {
            dw1 += __shfl_xor_sync(0xffffffffu, dw1, off);
            dr1 += __shfl_xor_sync(0xffffffffu, dr1, off);
            dw2 += __shfl_xor_sync(0xffffffffu, dw2, off);
            dr2 += __shfl_xor_sync(0xffffffffu, dr2, off);
        }
        const float w1 = __expf(dw1 * SCALE);
        const float e1 = __expf(dr1 * SCALE);
        const float w2 = has2 ? __expf(dw2 * SCALE) : 0.f;
        const float e2 = has2 ? __expf(dr2 * SCALE) : 0.f;
        sw += w1 + w2;
        sr += e1 + e2;
        cc += w1 * e1 + w2 * e2;

        awv[0] += w1 * v0.x + w2 * u0.x;  arv[0] += e1 * v0.x + e2 * u0.x;
        awv[1] += w1 * v0.y + w2 * u0.y;  arv[1] += e1 * v0.y + e2 * u0.y;
        awv[2] += w1 * v0.z + w2 * u0.z;  arv[2] += e1 * v0.z + e2 * u0.z;
        awv[3] += w1 * v0.w + w2 * u0.w;  arv[3] += e1 * v0.w + e2 * u0.w;
        awv[4] += w1 * v1.x + w2 * u1.x;  arv[4] += e1 * v1.x + e2 * u1.x;
        awv[5] += w1 * v1.y + w2 * u1.y;  arv[5] += e1 * v1.y + e2 * u1.y;
        awv[6] += w1 * v1.z + w2 * u1.z;  arv[6] += e1 * v1.z + e2 * u1.z;
        awv[7] += w1 * v1.w + w2 * u1.w;  arv[7] += e1 * v1.w + e2 * u1.w;
    }

    // Block reduction: warp w's lane l holds cols 8l..8l+7
    __shared__ float sh[NWARP][DIM];
    const int t = threadIdx.x;

#pragma unroll
    for (int j = 0; j < 8; ++j) sh[warp][lane * 8 + j] = awv[j];
    __syncthreads();
    {
        float s = 0.f;
#pragma unroll
        for (int w2 = 0; w2 < NWARP; ++w2) s += sh[w2][t];
        g_pwv[blockIdx.x][t] = s;
    }
    __syncthreads();
#pragma unroll
    for (int j = 0; j < 8; ++j) sh[warp][lane * 8 + j] = arv[j];
    __syncthreads();
    {
        float s = 0.f;
#pragma unroll
        for (int w2 = 0; w2 < NWARP; ++w2) s += sh[w2][t];
        g_prv[blockIdx.x][t] = s;
    }

    __shared__ float ssc[NWARP][3];
    if (lane == 0) { ssc[warp][0] = sw; ssc[warp][1] = sr; ssc[warp][2] = cc; }
    __syncthreads();
    if (t < 3) {
        float s = 0.f;
#pragma unroll
        for (int w2 = 0; w2 < NWARP; ++w2) s += ssc[w2][t];
        g_psc[blockIdx.x][t] = s;
    }
}

// ============================================================
// Single-launch tail: one block per output column (256 blocks,
// 128 threads). Thread i folds rows i, i+128, ... of the column
// plus the scalar partials; fixed-order shuffle+smem reduction
// (deterministic). Thread 0 writes out[col].
// ============================================================
__global__ __launch_bounds__(TAILT) void k_tail(const float* __restrict__ value,
                                                float* __restrict__ out) {
    const int col  = blockIdx.x;       // 0..255
    const int i    = threadIdx.x;      // 0..127
    const int lane = i & 31;
    const int wrp  = i >> 5;

    float wv = 0.f, rv = 0.f, s0 = 0.f, s1 = 0.f, s2 = 0.f;
    // rows i, i+128, i+256, (i+384 if < NB): at most 4 rows/thread.
#pragma unroll
    for (int p = 0; p < 4; ++p) {
        const int b = i + p * TAILT;
        if (b < NB) {
            wv += g_pwv[b][col];
            rv += g_prv[b][col];
            s0 += g_psc[b][0];
            s1 += g_psc[b][1];
            s2 += g_psc[b][2];
        }
    }

    // Warp reduction (fixed butterfly order -> deterministic).
#pragma unroll
    for (int off = 16; off > 0; off >>= 1) {
        wv += __shfl_xor_sync(0xffffffffu, wv, off);
        rv += __shfl_xor_sync(0xffffffffu, rv, off);
        s0 += __shfl_xor_sync(0xffffffffu, s0, off);
        s1 += __shfl_xor_sync(0xffffffffu, s1, off);
        s2 += __shfl_xor_sync(0xffffffffu, s2, off);
    }

    __shared__ float sred[4][5];
    if (lane == 0) {
        sred[wrp][0] = wv;
        sred[wrp][1] = rv;
        sred[wrp][2] = s0;
        sred[wrp][3] = s1;
        sred[wrp][4] = s2;
    }
    __syncthreads();
    if (i == 0) {
        float WV = (sred[0][0] + sred[1][0]) + (sred[2][0] + sred[3][0]);
        float RV = (sred[0][1] + sred[1][1]) + (sred[2][1] + sred[3][1]);
        float SW = (sred[0][2] + sred[1][2]) + (sred[2][2] + sred[3][2]);
        float SR = (sred[0][3] + sred[1][3]) + (sred[2][3] + sred[3][3]);
        float CC = (sred[0][4] + sred[1][4]) + (sred[2][4] + sred[3][4]);
        out[col] = RV / SR + (CC / (SW * SR)) * (value[col] - WV / SW);
    }
}

// ============================================================
extern "C" void kernel_launch(void* const* d_in, const int* in_sizes, int n_in,
                              void* d_out, int out_size) {
    const float* key   = (const float*)d_in[0];
    const float* value = (const float*)d_in[1];
    const float* query = (const float*)d_in[2];
    const float* Kmat  = (const float*)d_in[3];
    const float* Vmat  = (const float*)d_in[4];
    float*       out   = (float*)d_out;

    k_fused<<<NB, TPB>>>(Kmat, Vmat, key, query);
    k_tail<<<DIM, TAILT>>>(value, out);
}